// round 15
// baseline (speedup 1.0000x reference)
#include <cuda_runtime.h>
#include <cuda_fp16.h>
#include <cstdint>

#define B_      2
#define C_      192
#define C3_     576
#define H_      256
#define W_      256
#define HW_     65536
#define HEADS_  8
#define KSPLIT_ 4

// ---------------- scratch (device globals: allocation-free rule) ----------------
__device__ __half g_wqh [C3_ * C_];
__device__ __half g_wph [C_ * C_];
__device__ __half g_qkvh[(size_t)B_ * C3_ * HW_];
__device__ __half g_dwh [(size_t)B_ * C3_ * HW_];
__device__ __half g_av  [(size_t)B_ * C_ * HW_];
__device__ float  g_gramp[(size_t)KSPLIT_ * B_ * HEADS_ * C_ * C_];
__device__ __half g_attnh[(size_t)B_ * HEADS_ * C_ * C_];
__device__ float g_partq[B_ * C_ * 64];
__device__ float g_partk[B_ * C_ * 64];
__device__ float g_invq [B_ * C_ * 8];
__device__ float g_invk [B_ * C_ * 8];

// ---------------- mma / ldmatrix / cp.async helpers ----------------
__device__ __forceinline__ void ldsm4(unsigned* r, const void* p) {
    unsigned a = (unsigned)__cvta_generic_to_shared(p);
    asm volatile("ldmatrix.sync.aligned.m8n8.x4.shared.b16 {%0,%1,%2,%3}, [%4];"
                 : "=r"(r[0]), "=r"(r[1]), "=r"(r[2]), "=r"(r[3]) : "r"(a));
}
__device__ __forceinline__ void ldsm4t(unsigned* r, const void* p) {
    unsigned a = (unsigned)__cvta_generic_to_shared(p);
    asm volatile("ldmatrix.sync.aligned.m8n8.x4.trans.shared.b16 {%0,%1,%2,%3}, [%4];"
                 : "=r"(r[0]), "=r"(r[1]), "=r"(r[2]), "=r"(r[3]) : "r"(a));
}
__device__ __forceinline__ void ldsm2(unsigned* r, const void* p) {
    unsigned a = (unsigned)__cvta_generic_to_shared(p);
    asm volatile("ldmatrix.sync.aligned.m8n8.x2.shared.b16 {%0,%1}, [%2];"
                 : "=r"(r[0]), "=r"(r[1]) : "r"(a));
}
__device__ __forceinline__ void mma16816(float* c, const unsigned* a, const unsigned* b) {
    asm volatile("mma.sync.aligned.m16n8k16.row.col.f32.f16.f16.f32 "
                 "{%0,%1,%2,%3},{%4,%5,%6,%7},{%8,%9},{%0,%1,%2,%3};"
                 : "+f"(c[0]), "+f"(c[1]), "+f"(c[2]), "+f"(c[3])
                 : "r"(a[0]), "r"(a[1]), "r"(a[2]), "r"(a[3]), "r"(b[0]), "r"(b[1]));
}
__device__ __forceinline__ void cpa16(unsigned dst, const void* src) {
    asm volatile("cp.async.cg.shared.global [%0], [%1], 16;\n" :: "r"(dst), "l"(src));
}
#define CP_COMMIT() asm volatile("cp.async.commit_group;\n")
#define CP_WAIT1()  asm volatile("cp.async.wait_group 1;\n" ::: "memory")
#define CP_WAIT2()  asm volatile("cp.async.wait_group 2;\n" ::: "memory")

// ---------------- fp32 -> fp16 convert (weights only) ----------------
__global__ __launch_bounds__(256) void split_h_kernel(
    const float* __restrict__ in, __half* __restrict__ oh, int n)
{
    int i = (blockIdx.x * 256 + threadIdx.x) * 4;
    if (i < n) {
        float4 v = *(const float4*)(in + i);
        __half2 a; a.x = __float2half(v.x); a.y = __float2half(v.y);
        __half2 b; b.x = __float2half(v.z); b.y = __float2half(v.w);
        ((__half2*)(oh + i))[0] = a;
        ((__half2*)(oh + i))[1] = b;
    }
}

// =====================================================================
// QKV fused: C = Wq(fp16) @ X(fp32->fp16 in-kernel).
// BM=96 BN=128 BK=32, K=192 (6 stages). A: cp.async 3-ring.
// B: fp32 LDG one stage ahead -> convert -> STS fp16 (double buffer).
// 384 threads, warp tile 32x32.
// =====================================================================
__global__ __launch_bounds__(384, 2) void qkv_fused(
    const __half* __restrict__ Wq, const float* __restrict__ X,
    __half* __restrict__ Out)
{
    __shared__ alignas(16) __half Ash[3][96][40];
    __shared__ alignas(16) __half Bsh[2][32][136];

    const int z = blockIdx.z, bm = blockIdx.y * 96, bn = blockIdx.x * 128;
    const int tid = threadIdx.x, lane = tid & 31, w = tid >> 5;
    const int m0 = (w >> 2) * 32, n0 = (w & 3) * 32;

    // A loader: 384 16B-chunks, exactly 1 per thread
    const __half* asrc; unsigned adst;
    {
        int row = tid >> 2, c4 = tid & 3;
        asrc = Wq + (size_t)(bm + row) * C_ + c4 * 8;
        adst = (unsigned)__cvta_generic_to_shared(&Ash[0][row][c4 * 8]);
    }
    // B loader: 2048 float2 chunks, 6 per thread (last partial)
    const float* bsrc[6]; int brow_[6], bc2_[6]; bool bval[6];
#pragma unroll
    for (int it = 0; it < 6; ++it) {
        int idx = tid + it * 384;
        bval[it] = idx < 2048;
        if (idx >= 2048) idx = 2047;
        brow_[it] = idx >> 6;           // k-row within stage (0..31)
        bc2_[it]  = idx & 63;           // float2 column (0..63)
        bsrc[it] = X + ((size_t)z * C_ + brow_[it]) * HW_ + bn + bc2_[it] * 2;
    }

    float acc[2][4][4];
#pragma unroll
    for (int i = 0; i < 2; ++i)
#pragma unroll
        for (int j = 0; j < 4; ++j)
#pragma unroll
            for (int q = 0; q < 4; ++q) acc[i][j][q] = 0.f;

    float2 breg[6];
    // prologue: B stage 0 LDG, A stages 0,1 cp.async
#pragma unroll
    for (int it = 0; it < 6; ++it) if (bval[it]) breg[it] = __ldg((const float2*)bsrc[it]);
    cpa16(adst, asrc);              CP_COMMIT();
    cpa16(adst + 7680u, asrc + 32); CP_COMMIT();
#pragma unroll
    for (int it = 0; it < 6; ++it) if (bval[it]) {
        __half2 hv; hv.x = __float2half(breg[it].x); hv.y = __float2half(breg[it].y);
        *(__half2*)&Bsh[0][brow_[it]][bc2_[it] * 2] = hv;
    }
    CP_WAIT1();
    __syncthreads();

#pragma unroll 1
    for (int s = 0; s < 6; ++s) {
        // LDG next B stage
        if (s + 1 < 6) {
            const size_t off = (size_t)(s + 1) * 32 * HW_;
#pragma unroll
            for (int it = 0; it < 6; ++it) if (bval[it]) breg[it] = __ldg((const float2*)(bsrc[it] + off));
        }
        // MMA stage s
        const __half (*As)[40] = Ash[s % 3];
        const __half (*Bs)[136] = Bsh[s & 1];
#pragma unroll
        for (int kk = 0; kk < 32; kk += 16) {
            unsigned ah[2][4], bh[2][4];
            const int l15 = lane & 15;
            const int g = lane >> 3;
            const int brow = kk + ((g & 1) << 3) + (lane & 7);
#pragma unroll
            for (int mi = 0; mi < 2; ++mi)
                ldsm4(ah[mi], &As[m0 + mi * 16 + l15][kk + (lane >> 4) * 8]);
#pragma unroll
            for (int p = 0; p < 2; ++p) {
                const int bcol = n0 + p * 16 + ((g >> 1) << 3);
                ldsm4t(bh[p], &Bs[brow][bcol]);
            }
#pragma unroll
            for (int mi = 0; mi < 2; ++mi)
#pragma unroll
                for (int p = 0; p < 2; ++p)
#pragma unroll
                    for (int h2 = 0; h2 < 2; ++h2)
                        mma16816(acc[mi][p * 2 + h2], ah[mi], bh[p] + h2 * 2);
        }
        // prefetch A s+2, store B s+1
        if (s + 2 < 6) cpa16(adst + (unsigned)((s + 2) % 3) * 7680u, asrc + (s + 2) * 32);
        CP_COMMIT();
        if (s + 1 < 6) {
            __half* bb = &Bsh[(s + 1) & 1][0][0];
#pragma unroll
            for (int it = 0; it < 6; ++it) if (bval[it]) {
                __half2 hv; hv.x = __float2half(breg[it].x); hv.y = __float2half(breg[it].y);
                *(__half2*)(bb + brow_[it] * 136 + bc2_[it] * 2) = hv;
            }
            CP_WAIT1();
            __syncthreads();
        }
    }

#pragma unroll
    for (int mi = 0; mi < 2; ++mi)
#pragma unroll
        for (int ni = 0; ni < 4; ++ni) {
            const int r = bm + m0 + mi * 16 + (lane >> 2);
            const int cc = bn + n0 + ni * 8 + (lane & 3) * 2;
            const float* a = acc[mi][ni];
            __half2 v0; v0.x = __float2half(a[0]); v0.y = __float2half(a[1]);
            __half2 v1; v1.x = __float2half(a[2]); v1.y = __float2half(a[3]);
            __half* cp0 = Out + ((size_t)z * C3_ + r) * HW_ + cc;
            *(__half2*)cp0             = v0;
            *(__half2*)(cp0 + 8 * HW_) = v1;
        }
}

// ---------------- maps (AV / Proj) ----------------
struct AvMap {
    const __half *Ah, *B; __half *Cc;
    static constexpr int CMODE = 1;
    static constexpr size_t BSTRIDE32 = (size_t)4 << 16;
    __device__ const __half* aRowH(int z, int m) const { return Ah + (size_t)z * (C_ * C_) + (size_t)m * C_; }
    __device__ const __half* bRow(int z, int k) const {
        int b = z >> 3, h = z & 7;
        return B + ((size_t)(b * C3_ + 2 * C_ + h * 24 + (k >> 3)) << 16) + ((k & 7) << 13);
    }
    __device__ __half* cRow(int z, int m) const {
        int b = z >> 3, h = z & 7;
        return Cc + ((size_t)(b * C_ + h * 24 + (m >> 3)) << 16) + ((m & 7) << 13);
    }
    __device__ float*  cRowF(int z, int m) const { return nullptr; }
};
struct ProjMap {
    const __half *Ah, *B; float* C;
    static constexpr int CMODE = 2;
    static constexpr size_t BSTRIDE32 = (size_t)32 * HW_;
    __device__ const __half* aRowH(int z, int m) const { return Ah + (size_t)m * C_; }
    __device__ const __half* bRow(int z, int k) const { return B + ((size_t)z * C_ + k) * HW_; }
    __device__ float* cRowF(int z, int m) const { return C + ((size_t)z * C_ + m) * HW_; }
    __device__ __half* cRow(int z, int m) const { return nullptr; }
};

// =====================================================================
// fp16 MMA GEMM: C = Ah @ B.  BM=96 BN=128 BK=32, 4-stage cp.async ring,
// 384 threads (12 warps, warp tile 32x32), dynamic smem.
// =====================================================================
#define GEMM_ASTGB 7680u
#define GEMM_BSTGB 8704u
#define GEMM_SMEM  (4 * (GEMM_ASTGB + GEMM_BSTGB))

template <class Map>
__global__ __launch_bounds__(384, 2) void gemm_mma(const Map map, const int K)
{
    extern __shared__ char smraw[];
    __half* Abase = (__half*)smraw;
    __half* Bbase = (__half*)(smraw + 4 * GEMM_ASTGB);

    const int z = blockIdx.z, bm = blockIdx.y * 96, bn = blockIdx.x * 128;
    const int tid = threadIdx.x, lane = tid & 31, w = tid >> 5;
    const int m0 = (w >> 2) * 32, n0 = (w & 3) * 32;

    const __half* asrc; unsigned adst;
    {
        int row = tid >> 2, c4 = tid & 3;
        asrc = map.aRowH(z, bm + row) + c4 * 8;
        adst = (unsigned)__cvta_generic_to_shared(Abase + row * 40 + c4 * 8);
    }
    const __half* bsrc[2]; unsigned bdst[2]; bool bval[2];
#pragma unroll
    for (int it = 0; it < 2; ++it) {
        int idx = tid + it * 384;
        bval[it] = idx < 512;
        if (idx >= 512) idx = 511;
        int row = idx >> 4, c4 = idx & 15;
        bsrc[it] = map.bRow(z, row) + bn + c4 * 8;
        bdst[it] = (unsigned)__cvta_generic_to_shared(Bbase + row * 136 + c4 * 8);
    }

    float acc[2][4][4];
#pragma unroll
    for (int i = 0; i < 2; ++i)
#pragma unroll
        for (int j = 0; j < 4; ++j)
#pragma unroll
            for (int q = 0; q < 4; ++q) acc[i][j][q] = 0.f;

    const int nStage = K >> 5;
#pragma unroll
    for (int p = 0; p < 3; ++p) {
        if (p < nStage) {
            cpa16(adst + p * GEMM_ASTGB, asrc + p * 32);
#pragma unroll
            for (int it = 0; it < 2; ++it) if (bval[it]) cpa16(bdst[it] + p * GEMM_BSTGB, bsrc[it] + (size_t)p * Map::BSTRIDE32);
        }
        CP_COMMIT();
    }

#pragma unroll 1
    for (int s = 0; s < nStage; ++s) {
        CP_WAIT2();
        __syncthreads();
        if (s + 3 < nStage) {
            const unsigned b4 = (unsigned)((s + 3) & 3);
            const int ka = (s + 3) * 32;
            const size_t kb = (size_t)(s + 3) * Map::BSTRIDE32;
            cpa16(adst + b4 * GEMM_ASTGB, asrc + ka);
#pragma unroll
            for (int it = 0; it < 2; ++it) if (bval[it]) cpa16(bdst[it] + b4 * GEMM_BSTGB, bsrc[it] + kb);
        }
        CP_COMMIT();
        const __half* As  = Abase + (s & 3) * 3840;
        const __half* Bsp = Bbase + (s & 3) * 4352;
#pragma unroll
        for (int kk = 0; kk < 32; kk += 16) {
            unsigned ah[2][4], bh[2][4];
            const int l15 = lane & 15;
            const int g = lane >> 3;
            const int brow = kk + ((g & 1) << 3) + (lane & 7);
#pragma unroll
            for (int mi = 0; mi < 2; ++mi)
                ldsm4(ah[mi], As + (m0 + mi * 16 + l15) * 40 + kk + (lane >> 4) * 8);
#pragma unroll
            for (int p = 0; p < 2; ++p) {
                const int bcol = n0 + p * 16 + ((g >> 1) << 3);
                ldsm4t(bh[p], Bsp + brow * 136 + bcol);
            }
#pragma unroll
            for (int mi = 0; mi < 2; ++mi)
#pragma unroll
                for (int p = 0; p < 2; ++p)
#pragma unroll
                    for (int h2 = 0; h2 < 2; ++h2)
                        mma16816(acc[mi][p * 2 + h2], ah[mi], bh[p] + h2 * 2);
        }
    }

#pragma unroll
    for (int mi = 0; mi < 2; ++mi)
#pragma unroll
        for (int ni = 0; ni < 4; ++ni) {
            const int r = bm + m0 + mi * 16 + (lane >> 2);
            const int cc = bn + n0 + ni * 8 + (lane & 3) * 2;
            const float* a = acc[mi][ni];
            if constexpr (Map::CMODE == 1) {
                __half2 v0; v0.x = __float2half(a[0]); v0.y = __float2half(a[1]);
                __half2 v1; v1.x = __float2half(a[2]); v1.y = __float2half(a[3]);
                *(__half2*)(map.cRow(z, r) + cc)     = v0;
                *(__half2*)(map.cRow(z, r + 8) + cc) = v1;
            } else {
                *(float2*)(map.cRowF(z, r) + cc)     = make_float2(a[0], a[1]);
                *(float2*)(map.cRowF(z, r + 8) + cc) = make_float2(a[2], a[3]);
            }
        }
}

// =====================================================================
// Gram: C[i,j] = sum_n q[i,n]*k[j,n] (fp16). BM=BN=96 BK=32,
// split-K=4, 4-stage cp.async ring, dynamic smem, ldsm4 B-frags.
// =====================================================================
#define GRAM_STGB 7680u
#define GRAM_SMEM (4 * 2 * GRAM_STGB)

__global__ __launch_bounds__(256, 2) void gram_mma(
    const __half* __restrict__ dwh, float* __restrict__ gramp)
{
    extern __shared__ char smraw[];
    __half* Abase = (__half*)smraw;
    __half* Bbase = (__half*)(smraw + 4 * GRAM_STGB);

    constexpr int KS_LEN = 8192 / KSPLIT_;
    constexpr int NSTG = KS_LEN / 32;

    const int z = blockIdx.z;
    const int ks = z & (KSPLIT_ - 1), bh_ = z / KSPLIT_;
    const int h = bh_ & 7, b = bh_ >> 3;
    const int bi = blockIdx.y * 96, bj = blockIdx.x * 96;
    const int tid = threadIdx.x, lane = tid & 31, w = tid >> 5;
    const int m0 = (w >> 2) * 48, n0 = (w & 3) * 24;
    const int kbase = ks * KS_LEN;

    const __half* src[3]; unsigned dst[3];
#pragma unroll
    for (int it = 0; it < 3; ++it) {
        int idx = tid + it * 256;
        int which = idx / 384, w2 = idx % 384;
        int row = w2 >> 2, c4 = w2 & 3;
        size_t off;
        if (which == 0) {
            int qi = bi + row;
            off = ((size_t)(b * C3_ + h * 24 + (qi >> 3)) << 16) + ((size_t)(qi & 7) << 13);
        } else {
            int kj = bj + row;
            off = ((size_t)(b * C3_ + C_ + h * 24 + (kj >> 3)) << 16) + ((size_t)(kj & 7) << 13);
        }
        src[it] = dwh + off + kbase + c4 * 8;
        __half* d = (which == 0 ? Abase : Bbase) + row * 40 + c4 * 8;
        dst[it] = (unsigned)__cvta_generic_to_shared(d);
    }

    float acc[3][3][4];
#pragma unroll
    for (int i = 0; i < 3; ++i)
#pragma unroll
        for (int j = 0; j < 3; ++j)
#pragma unroll
            for (int q = 0; q < 4; ++q) acc[i][j][q] = 0.f;

#pragma unroll
    for (int p = 0; p < 3; ++p) {
#pragma unroll
        for (int it = 0; it < 3; ++it) cpa16(dst[it] + p * GRAM_STGB, src[it] + p * 32);
        CP_COMMIT();
    }

#pragma unroll 1
    for (int s = 0; s < NSTG; ++s) {
        CP_WAIT2();
        __syncthreads();
        if (s + 3 < NSTG) {
            const unsigned b4 = (unsigned)((s + 3) & 3);
            const int ka = (s + 3) * 32;
#pragma unroll
            for (int it = 0; it < 3; ++it) cpa16(dst[it] + b4 * GRAM_STGB, src[it] + ka);
        }
        CP_COMMIT();
        const __half* As = Abase + (s & 3) * 3840;
        const __half* Bs = Bbase + (s & 3) * 3840;
#pragma unroll
        for (int kk = 0; kk < 32; kk += 16) {
            unsigned ah[3][4], bph[4], b2h[2];
            const int l15 = lane & 15;
            const int g = lane >> 3;
#pragma unroll
            for (int mi = 0; mi < 3; ++mi)
                ldsm4(ah[mi], As + (m0 + mi * 16 + l15) * 40 + kk + (lane >> 4) * 8);
            {
                const int brow = n0 + ((g >> 1) << 3) + (lane & 7);
                const int bcol = kk + ((g & 1) << 3);
                ldsm4(bph, Bs + brow * 40 + bcol);
                ldsm2(b2h, Bs + (n0 + 16 + (l15 & 7)) * 40 + kk + ((l15 >> 3) << 3));
            }
#pragma unroll
            for (int mi = 0; mi < 3; ++mi) {
#pragma unroll
                for (int h2 = 0; h2 < 2; ++h2)
                    mma16816(acc[mi][h2], ah[mi], bph + h2 * 2);
                mma16816(acc[mi][2], ah[mi], b2h);
            }
        }
    }

    float* gp = gramp + ((size_t)ks * (B_ * HEADS_) + bh_) * (C_ * C_);
#pragma unroll
    for (int mi = 0; mi < 3; ++mi)
#pragma unroll
        for (int ni = 0; ni < 3; ++ni) {
            const int r = bi + m0 + mi * 16 + (lane >> 2);
            const int cc = bj + n0 + ni * 8 + (lane & 3) * 2;
            const float* a = acc[mi][ni];
            *(float2*)(gp + (size_t)r * C_ + cc)       = make_float2(a[0], a[1]);
            *(float2*)(gp + (size_t)(r + 8) * C_ + cc) = make_float2(a[2], a[3]);
        }
}

// ---------------- depthwise 3x3 (fp16 in/out) + norm partials -----------------
__global__ __launch_bounds__(256) void dw_kernel(
    const __half* __restrict__ inh, const float* __restrict__ dww,
    __half* __restrict__ outh,
    float* __restrict__ partq, float* __restrict__ partk)
{
    const int chg = blockIdx.z;
    const int c = chg % C3_;
    const int b = chg / C3_;
    const size_t base = (size_t)chg << 16;

    float w[9];
#pragma unroll
    for (int i = 0; i < 9; ++i) w[i] = __ldg(&dww[c * 9 + i]);

    __shared__ float s[34][34];
    const int ox = blockIdx.x * 32 - 1, oy = blockIdx.y * 32 - 1;
    for (int t = threadIdx.x; t < 34 * 34; t += 256) {
        int lx = t % 34, ly = t / 34;
        int gx = ox + lx, gy = oy + ly;
        float v = 0.f;
        if ((unsigned)gx < W_ && (unsigned)gy < H_) v = __half2float(inh[base + gy * W_ + gx]);
        s[ly][lx] = v;
    }
    __syncthreads();

    const int tx = threadIdx.x & 31, ty0 = threadIdx.x >> 5;
    float ss = 0.f;
#pragma unroll
    for (int r = 0; r < 4; ++r) {
        int ly = ty0 + 8 * r;
        float acc = s[ly + 0][tx + 0] * w[0] + s[ly + 0][tx + 1] * w[1] + s[ly + 0][tx + 2] * w[2]
                  + s[ly + 1][tx + 0] * w[3] + s[ly + 1][tx + 1] * w[4] + s[ly + 1][tx + 2] * w[5]
                  + s[ly + 2][tx + 0] * w[6] + s[ly + 2][tx + 1] * w[7] + s[ly + 2][tx + 2] * w[8];
        ss += acc * acc;
        size_t sp = (size_t)(blockIdx.y * 32 + ly) * W_ + blockIdx.x * 32 + tx;
        outh[base + sp] = __float2half(acc);
    }

    if (c < 2 * C_) {
        __shared__ float red[8];
#pragma unroll
        for (int o = 16; o > 0; o >>= 1) ss += __shfl_xor_sync(0xffffffffu, ss, o);
        if ((threadIdx.x & 31) == 0) red[threadIdx.x >> 5] = ss;
        __syncthreads();
        if (threadIdx.x == 0) {
            float tot = 0.f;
#pragma unroll
            for (int i = 0; i < 8; ++i) tot += red[i];
            if (c < C_)
                partq[((b * C_ + c) * 8 + blockIdx.y) * 8 + blockIdx.x] = tot;
            else
                partk[((b * C_ + (c - C_)) * 8 + blockIdx.y) * 8 + blockIdx.x] = tot;
        }
    }
}

__global__ void norms_finish(
    const float* __restrict__ partq, const float* __restrict__ partk,
    float* __restrict__ invq, float* __restrict__ invk)
{
    int idx = blockIdx.x * blockDim.x + threadIdx.x;
    if (idx < B_ * C_ * 8) {
        float sq = 0.f, sk = 0.f;
#pragma unroll
        for (int i = 0; i < 8; ++i) { sq += partq[idx * 8 + i]; sk += partk[idx * 8 + i]; }
        invq[idx] = 1.f / fmaxf(sqrtf(sq), 1e-12f);
        invk[idx] = 1.f / fmaxf(sqrtf(sk), 1e-12f);
    }
}

// ---------------- split-K reduce + scale + softmax -> fp16 ---------------
__global__ void softmax_kernel(
    const float* __restrict__ gramp, const float* __restrict__ invq,
    const float* __restrict__ invk, const float* __restrict__ temp,
    __half* __restrict__ attnh)
{
    const int i = blockIdx.x % C_;
    const int bh = blockIdx.x / C_;
    const int head = bh & 7, b = bh >> 3;
    const int j = threadIdx.x;

    const long long base = (long long)bh * (C_ * C_) + i * C_ + j;
    float s = 0.f;
#pragma unroll
    for (int ks = 0; ks < KSPLIT_; ++ks)
        s += gramp[(long long)ks * (B_ * HEADS_ * C_ * C_) + base];

    s *= invq[(b * C_ + head * 24 + (i >> 3)) * 8 + (i & 7)]
       * invk[(b * C_ + head * 24 + (j >> 3)) * 8 + (j & 7)]
       * temp[head];

    __shared__ float red[8];
    float m = s;
#pragma unroll
    for (int o = 16; o > 0; o >>= 1) m = fmaxf(m, __shfl_xor_sync(0xffffffffu, m, o));
    if ((threadIdx.x & 31) == 0) red[threadIdx.x >> 5] = m;
    __syncthreads();
    m = fmaxf(fmaxf(fmaxf(red[0], red[1]), fmaxf(red[2], red[3])), fmaxf(red[4], red[5]));

    float p = expf(s - m);
    float sum = p;
#pragma unroll
    for (int o = 16; o > 0; o >>= 1) sum += __shfl_xor_sync(0xffffffffu, sum, o);
    __syncthreads();
    if ((threadIdx.x & 31) == 0) red[threadIdx.x >> 5] = sum;
    __syncthreads();
    sum = red[0] + red[1] + red[2] + red[3] + red[4] + red[5];

    attnh[base] = __float2half(p / sum);
}

// ---------------- launch -------------------------------------------------------
extern "C" void kernel_launch(void* const* d_in, const int* in_sizes, int n_in,
                              void* d_out, int out_size)
{
    const float* x      = (const float*)d_in[0];
    const float* qkv_w  = (const float*)d_in[1];
    const float* dw_w   = (const float*)d_in[2];
    const float* proj_w = (const float*)d_in[3];
    const float* temp   = (const float*)d_in[4];
    float* out = (float*)d_out;

    __half *wqh, *wph, *qkvh, *dwh, *av, *attnh;
    float *gramp, *partq, *partk, *invq, *invk;
    cudaGetSymbolAddress((void**)&wqh,  g_wqh);
    cudaGetSymbolAddress((void**)&wph,  g_wph);
    cudaGetSymbolAddress((void**)&qkvh, g_qkvh);
    cudaGetSymbolAddress((void**)&dwh,  g_dwh);
    cudaGetSymbolAddress((void**)&av,   g_av);
    cudaGetSymbolAddress((void**)&attnh, g_attnh);
    cudaGetSymbolAddress((void**)&gramp, g_gramp);
    cudaGetSymbolAddress((void**)&partq, g_partq);
    cudaGetSymbolAddress((void**)&partk, g_partk);
    cudaGetSymbolAddress((void**)&invq,  g_invq);
    cudaGetSymbolAddress((void**)&invk,  g_invk);

    cudaFuncSetAttribute(gemm_mma<AvMap>,   cudaFuncAttributeMaxDynamicSharedMemorySize, GEMM_SMEM);
    cudaFuncSetAttribute(gemm_mma<ProjMap>, cudaFuncAttributeMaxDynamicSharedMemorySize, GEMM_SMEM);
    cudaFuncSetAttribute(gram_mma,          cudaFuncAttributeMaxDynamicSharedMemorySize, GRAM_SMEM);

    // 0) weight fp16 converts (x conversion fused into qkv_fused)
    split_h_kernel<<<(C3_ * C_ / 4 + 255) / 256, 256>>>(qkv_w, wqh, C3_ * C_);
    split_h_kernel<<<(C_ * C_ / 4 + 255) / 256, 256>>>(proj_w, wph, C_ * C_);

    // 1) qkv = qkv_w @ x   (fp32 x converted in-kernel)
    qkv_fused<<<dim3(HW_ / 128, C3_ / 96, B_), 384>>>(wqh, x, qkvh);
    // 2) depthwise 3x3 + norm partials
    dw_kernel<<<dim3(W_ / 32, H_ / 32, B_ * C3_), 256>>>(qkvh, dw_w, dwh, partq, partk);
    // 3) norms
    norms_finish<<<(B_ * C_ * 8 + 255) / 256, 256>>>(partq, partk, invq, invk);
    // 4) gram partials (split-K = 4)
    gram_mma<<<dim3(2, 2, B_ * HEADS_ * KSPLIT_), 256, GRAM_SMEM>>>(dwh, gramp);
    // 5) softmax
    softmax_kernel<<<B_ * HEADS_ * C_, C_>>>(gramp, invq, invk, temp, attnh);
    // 6) av = attn @ v
    {
        AvMap m{attnh, dwh, av};
        gemm_mma<AvMap><<<dim3(HW_ / HEADS_ / 128, C_ / 96, B_ * HEADS_), 384, GEMM_SMEM>>>(m, C_);
    }
    // 7) out = proj_w @ av
    {
        ProjMap m{wph, av, out};
        gemm_mma<ProjMap><<<dim3(HW_ / 128, C_ / 96, B_), 384, GEMM_SMEM>>>(m, C_);
    }
}

// round 16
// speedup vs baseline: 1.3793x; 1.3793x over previous
#include <cuda_runtime.h>
#include <cuda_fp16.h>
#include <cstdint>

#define B_      2
#define C_      192
#define C3_     576
#define H_      256
#define W_      256
#define HW_     65536
#define HEADS_  8
#define KSPLIT_ 4

// ---------------- scratch (device globals: allocation-free rule) ----------------
__device__ __half g_xh  [(size_t)B_ * C_ * HW_];
__device__ __half g_wqh [C3_ * C_];
__device__ __half g_wph [C_ * C_];
__device__ __half g_qkvh[(size_t)B_ * C3_ * HW_];
__device__ __half g_dwh [(size_t)B_ * C3_ * HW_];
__device__ __half g_av  [(size_t)B_ * C_ * HW_];
__device__ float  g_gramp[(size_t)KSPLIT_ * B_ * HEADS_ * C_ * C_];
__device__ __half g_attnh[(size_t)B_ * HEADS_ * C_ * C_];
__device__ float g_partq[B_ * C_ * 16];
__device__ float g_partk[B_ * C_ * 16];
__device__ float g_invq [B_ * C_ * 8];
__device__ float g_invk [B_ * C_ * 8];

// ---------------- mma / ldmatrix / cp.async helpers ----------------
__device__ __forceinline__ void ldsm4(unsigned* r, const void* p) {
    unsigned a = (unsigned)__cvta_generic_to_shared(p);
    asm volatile("ldmatrix.sync.aligned.m8n8.x4.shared.b16 {%0,%1,%2,%3}, [%4];"
                 : "=r"(r[0]), "=r"(r[1]), "=r"(r[2]), "=r"(r[3]) : "r"(a));
}
__device__ __forceinline__ void ldsm4t(unsigned* r, const void* p) {
    unsigned a = (unsigned)__cvta_generic_to_shared(p);
    asm volatile("ldmatrix.sync.aligned.m8n8.x4.trans.shared.b16 {%0,%1,%2,%3}, [%4];"
                 : "=r"(r[0]), "=r"(r[1]), "=r"(r[2]), "=r"(r[3]) : "r"(a));
}
__device__ __forceinline__ void ldsm2(unsigned* r, const void* p) {
    unsigned a = (unsigned)__cvta_generic_to_shared(p);
    asm volatile("ldmatrix.sync.aligned.m8n8.x2.shared.b16 {%0,%1}, [%2];"
                 : "=r"(r[0]), "=r"(r[1]) : "r"(a));
}
__device__ __forceinline__ void mma16816(float* c, const unsigned* a, const unsigned* b) {
    asm volatile("mma.sync.aligned.m16n8k16.row.col.f32.f16.f16.f32 "
                 "{%0,%1,%2,%3},{%4,%5,%6,%7},{%8,%9},{%0,%1,%2,%3};"
                 : "+f"(c[0]), "+f"(c[1]), "+f"(c[2]), "+f"(c[3])
                 : "r"(a[0]), "r"(a[1]), "r"(a[2]), "r"(a[3]), "r"(b[0]), "r"(b[1]));
}
__device__ __forceinline__ void cpa16(unsigned dst, const void* src) {
    asm volatile("cp.async.cg.shared.global [%0], [%1], 16;\n" :: "r"(dst), "l"(src));
}
#define CP_COMMIT() asm volatile("cp.async.commit_group;\n")
#define CP_WAIT2()  asm volatile("cp.async.wait_group 2;\n" ::: "memory")

// ---------------- fp32 -> fp16 convert ----------------
__global__ __launch_bounds__(256) void split_h_kernel(
    const float* __restrict__ in, __half* __restrict__ oh, int n)
{
    int i = (blockIdx.x * 256 + threadIdx.x) * 4;
    if (i < n) {
        float4 v = *(const float4*)(in + i);
        __half2 a; a.x = __float2half(v.x); a.y = __float2half(v.y);
        __half2 b; b.x = __float2half(v.z); b.y = __float2half(v.w);
        ((__half2*)(oh + i))[0] = a;
        ((__half2*)(oh + i))[1] = b;
    }
}

// ---------------- maps ----------------
struct QkvMap {
    const __half *Ah, *B; __half *Cc;
    static constexpr int CMODE = 1;
    static constexpr size_t BSTRIDE32 = (size_t)32 * HW_;
    __device__ const __half* aRowH(int z, int m) const { return Ah + (size_t)m * C_; }
    __device__ const __half* bRow(int z, int k) const { return B + ((size_t)z * C_ + k) * HW_; }
    __device__ __half* cRow(int z, int m) const { return Cc + ((size_t)z * C3_ + m) * HW_; }
    __device__ float*  cRowF(int z, int m) const { return nullptr; }
};
struct AvMap {
    const __half *Ah, *B; __half *Cc;
    static constexpr int CMODE = 1;
    static constexpr size_t BSTRIDE32 = (size_t)4 << 16;
    __device__ const __half* aRowH(int z, int m) const { return Ah + (size_t)z * (C_ * C_) + (size_t)m * C_; }
    __device__ const __half* bRow(int z, int k) const {
        int b = z >> 3, h = z & 7;
        return B + ((size_t)(b * C3_ + 2 * C_ + h * 24 + (k >> 3)) << 16) + ((k & 7) << 13);
    }
    __device__ __half* cRow(int z, int m) const {
        int b = z >> 3, h = z & 7;
        return Cc + ((size_t)(b * C_ + h * 24 + (m >> 3)) << 16) + ((m & 7) << 13);
    }
    __device__ float*  cRowF(int z, int m) const { return nullptr; }
};
struct ProjMap {
    const __half *Ah, *B; float* C;
    static constexpr int CMODE = 2;
    static constexpr size_t BSTRIDE32 = (size_t)32 * HW_;
    __device__ const __half* aRowH(int z, int m) const { return Ah + (size_t)m * C_; }
    __device__ const __half* bRow(int z, int k) const { return B + ((size_t)z * C_ + k) * HW_; }
    __device__ float* cRowF(int z, int m) const { return C + ((size_t)z * C_ + m) * HW_; }
    __device__ __half* cRow(int z, int m) const { return nullptr; }
};

// =====================================================================
// fp16 MMA GEMM: C = Ah @ B.  BM=96 BN=128 BK=32, 4-stage cp.async ring,
// 384 threads (12 warps, warp tile 32x32), dynamic smem.
// =====================================================================
#define GEMM_ASTGB 7680u
#define GEMM_BSTGB 8704u
#define GEMM_SMEM  (4 * (GEMM_ASTGB + GEMM_BSTGB))

template <class Map>
__global__ __launch_bounds__(384, 2) void gemm_mma(const Map map, const int K)
{
    extern __shared__ char smraw[];
    __half* Abase = (__half*)smraw;
    __half* Bbase = (__half*)(smraw + 4 * GEMM_ASTGB);

    const int z = blockIdx.z, bm = blockIdx.y * 96, bn = blockIdx.x * 128;
    const int tid = threadIdx.x, lane = tid & 31, w = tid >> 5;
    const int m0 = (w >> 2) * 32, n0 = (w & 3) * 32;

    const __half* asrc; unsigned adst;
    {
        int row = tid >> 2, c4 = tid & 3;
        asrc = map.aRowH(z, bm + row) + c4 * 8;
        adst = (unsigned)__cvta_generic_to_shared(Abase + row * 40 + c4 * 8);
    }
    const __half* bsrc[2]; unsigned bdst[2]; bool bval[2];
#pragma unroll
    for (int it = 0; it < 2; ++it) {
        int idx = tid + it * 384;
        bval[it] = idx < 512;
        if (idx >= 512) idx = 511;
        int row = idx >> 4, c4 = idx & 15;
        bsrc[it] = map.bRow(z, row) + bn + c4 * 8;
        bdst[it] = (unsigned)__cvta_generic_to_shared(Bbase + row * 136 + c4 * 8);
    }

    float acc[2][4][4];
#pragma unroll
    for (int i = 0; i < 2; ++i)
#pragma unroll
        for (int j = 0; j < 4; ++j)
#pragma unroll
            for (int q = 0; q < 4; ++q) acc[i][j][q] = 0.f;

    const int nStage = K >> 5;
#pragma unroll
    for (int p = 0; p < 3; ++p) {
        if (p < nStage) {
            cpa16(adst + p * GEMM_ASTGB, asrc + p * 32);
#pragma unroll
            for (int it = 0; it < 2; ++it) if (bval[it]) cpa16(bdst[it] + p * GEMM_BSTGB, bsrc[it] + (size_t)p * Map::BSTRIDE32);
        }
        CP_COMMIT();
    }

#pragma unroll 1
    for (int s = 0; s < nStage; ++s) {
        CP_WAIT2();
        __syncthreads();
        if (s + 3 < nStage) {
            const unsigned b4 = (unsigned)((s + 3) & 3);
            const int ka = (s + 3) * 32;
            const size_t kb = (size_t)(s + 3) * Map::BSTRIDE32;
            cpa16(adst + b4 * GEMM_ASTGB, asrc + ka);
#pragma unroll
            for (int it = 0; it < 2; ++it) if (bval[it]) cpa16(bdst[it] + b4 * GEMM_BSTGB, bsrc[it] + kb);
        }
        CP_COMMIT();
        const __half* As  = Abase + (s & 3) * 3840;
        const __half* Bsp = Bbase + (s & 3) * 4352;
#pragma unroll
        for (int kk = 0; kk < 32; kk += 16) {
            unsigned ah[2][4], bh[2][4];
            const int l15 = lane & 15;
            const int g = lane >> 3;
            const int brow = kk + ((g & 1) << 3) + (lane & 7);
#pragma unroll
            for (int mi = 0; mi < 2; ++mi)
                ldsm4(ah[mi], As + (m0 + mi * 16 + l15) * 40 + kk + (lane >> 4) * 8);
#pragma unroll
            for (int p = 0; p < 2; ++p) {
                const int bcol = n0 + p * 16 + ((g >> 1) << 3);
                ldsm4t(bh[p], Bsp + brow * 136 + bcol);
            }
#pragma unroll
            for (int mi = 0; mi < 2; ++mi)
#pragma unroll
                for (int p = 0; p < 2; ++p)
#pragma unroll
                    for (int h2 = 0; h2 < 2; ++h2)
                        mma16816(acc[mi][p * 2 + h2], ah[mi], bh[p] + h2 * 2);
        }
    }

#pragma unroll
    for (int mi = 0; mi < 2; ++mi)
#pragma unroll
        for (int ni = 0; ni < 4; ++ni) {
            const int r = bm + m0 + mi * 16 + (lane >> 2);
            const int cc = bn + n0 + ni * 8 + (lane & 3) * 2;
            const float* a = acc[mi][ni];
            if constexpr (Map::CMODE == 1) {
                __half2 v0; v0.x = __float2half(a[0]); v0.y = __float2half(a[1]);
                __half2 v1; v1.x = __float2half(a[2]); v1.y = __float2half(a[3]);
                *(__half2*)(map.cRow(z, r) + cc)     = v0;
                *(__half2*)(map.cRow(z, r + 8) + cc) = v1;
            } else {
                *(float2*)(map.cRowF(z, r) + cc)     = make_float2(a[0], a[1]);
                *(float2*)(map.cRowF(z, r + 8) + cc) = make_float2(a[2], a[3]);
            }
        }
}

// =====================================================================
// Gram: C[i,j] = sum_n q[i,n]*k[j,n] (fp16). BM=BN=96 BK=32,
// split-K=4, 4-stage cp.async ring, dynamic smem, ldsm4 B-frags.
// =====================================================================
#define GRAM_STGB 7680u
#define GRAM_SMEM (4 * 2 * GRAM_STGB)

__global__ __launch_bounds__(256, 2) void gram_mma(
    const __half* __restrict__ dwh, float* __restrict__ gramp)
{
    extern __shared__ char smraw[];
    __half* Abase = (__half*)smraw;
    __half* Bbase = (__half*)(smraw + 4 * GRAM_STGB);

    constexpr int KS_LEN = 8192 / KSPLIT_;
    constexpr int NSTG = KS_LEN / 32;

    const int z = blockIdx.z;
    const int ks = z & (KSPLIT_ - 1), bh_ = z / KSPLIT_;
    const int h = bh_ & 7, b = bh_ >> 3;
    const int bi = blockIdx.y * 96, bj = blockIdx.x * 96;
    const int tid = threadIdx.x, lane = tid & 31, w = tid >> 5;
    const int m0 = (w >> 2) * 48, n0 = (w & 3) * 24;
    const int kbase = ks * KS_LEN;

    const __half* src[3]; unsigned dst[3];
#pragma unroll
    for (int it = 0; it < 3; ++it) {
        int idx = tid + it * 256;
        int which = idx / 384, w2 = idx % 384;
        int row = w2 >> 2, c4 = w2 & 3;
        size_t off;
        if (which == 0) {
            int qi = bi + row;
            off = ((size_t)(b * C3_ + h * 24 + (qi >> 3)) << 16) + ((size_t)(qi & 7) << 13);
        } else {
            int kj = bj + row;
            off = ((size_t)(b * C3_ + C_ + h * 24 + (kj >> 3)) << 16) + ((size_t)(kj & 7) << 13);
        }
        src[it] = dwh + off + kbase + c4 * 8;
        __half* d = (which == 0 ? Abase : Bbase) + row * 40 + c4 * 8;
        dst[it] = (unsigned)__cvta_generic_to_shared(d);
    }

    float acc[3][3][4];
#pragma unroll
    for (int i = 0; i < 3; ++i)
#pragma unroll
        for (int j = 0; j < 3; ++j)
#pragma unroll
            for (int q = 0; q < 4; ++q) acc[i][j][q] = 0.f;

#pragma unroll
    for (int p = 0; p < 3; ++p) {
#pragma unroll
        for (int it = 0; it < 3; ++it) cpa16(dst[it] + p * GRAM_STGB, src[it] + p * 32);
        CP_COMMIT();
    }

#pragma unroll 1
    for (int s = 0; s < NSTG; ++s) {
        CP_WAIT2();
        __syncthreads();
        if (s + 3 < NSTG) {
            const unsigned b4 = (unsigned)((s + 3) & 3);
            const int ka = (s + 3) * 32;
#pragma unroll
            for (int it = 0; it < 3; ++it) cpa16(dst[it] + b4 * GRAM_STGB, src[it] + ka);
        }
        CP_COMMIT();
        const __half* As = Abase + (s & 3) * 3840;
        const __half* Bs = Bbase + (s & 3) * 3840;
#pragma unroll
        for (int kk = 0; kk < 32; kk += 16) {
            unsigned ah[3][4], bph[4], b2h[2];
            const int l15 = lane & 15;
            const int g = lane >> 3;
#pragma unroll
            for (int mi = 0; mi < 3; ++mi)
                ldsm4(ah[mi], As + (m0 + mi * 16 + l15) * 40 + kk + (lane >> 4) * 8);
            {
                const int brow = n0 + ((g >> 1) << 3) + (lane & 7);
                const int bcol = kk + ((g & 1) << 3);
                ldsm4(bph, Bs + brow * 40 + bcol);
                ldsm2(b2h, Bs + (n0 + 16 + (l15 & 7)) * 40 + kk + ((l15 >> 3) << 3));
            }
#pragma unroll
            for (int mi = 0; mi < 3; ++mi) {
#pragma unroll
                for (int h2 = 0; h2 < 2; ++h2)
                    mma16816(acc[mi][h2], ah[mi], bph + h2 * 2);
                mma16816(acc[mi][2], ah[mi], b2h);
            }
        }
    }

    float* gp = gramp + ((size_t)ks * (B_ * HEADS_) + bh_) * (C_ * C_);
#pragma unroll
    for (int mi = 0; mi < 3; ++mi)
#pragma unroll
        for (int ni = 0; ni < 3; ++ni) {
            const int r = bi + m0 + mi * 16 + (lane >> 2);
            const int cc = bj + n0 + ni * 8 + (lane & 3) * 2;
            const float* a = acc[mi][ni];
            *(float2*)(gp + (size_t)r * C_ + cc)       = make_float2(a[0], a[1]);
            *(float2*)(gp + (size_t)(r + 8) * C_ + cc) = make_float2(a[2], a[3]);
        }
}

// =====================================================================
// Depthwise 3x3: full-width band tiles (256 wide x 16 high), sliding
// window registers, coalesced loads/stores, fused norm partials.
// grid: (16 bands, B*576 channels), 256 threads.
// =====================================================================
__global__ __launch_bounds__(256) void dw_kernel(
    const __half* __restrict__ inh, const float* __restrict__ dww,
    __half* __restrict__ outh,
    float* __restrict__ partq, float* __restrict__ partk)
{
    const int chg = blockIdx.y;
    const int c = chg % C3_;
    const int b = chg / C3_;
    const size_t base = (size_t)chg << 16;
    const int y0 = blockIdx.x * 16;
    const int tid = threadIdx.x;

    float w[9];
#pragma unroll
    for (int i = 0; i < 9; ++i) w[i] = __ldg(&dww[c * 9 + i]);

    __shared__ float s[18][258];

    // zero halo columns (always out of image: x=-1 and x=256)
    if (tid < 36) {
        int r = tid >> 1, hc = (tid & 1) ? 257 : 0;
        s[r][hc] = 0.f;
    }
    // load 18 rows x 256 cols, coalesced; row y0-1+r
#pragma unroll
    for (int r = 0; r < 18; ++r) {
        int gy = y0 - 1 + r;
        float v = 0.f;
        if ((unsigned)gy < H_) v = __half2float(inh[base + (size_t)gy * W_ + tid]);
        s[r][tid + 1] = v;
    }
    __syncthreads();

    float a0 = s[0][tid], a1 = s[0][tid + 1], a2 = s[0][tid + 2];
    float b0 = s[1][tid], b1 = s[1][tid + 1], b2 = s[1][tid + 2];
    float ss = 0.f;
#pragma unroll
    for (int r = 0; r < 16; ++r) {
        float c0 = s[r + 2][tid], c1 = s[r + 2][tid + 1], c2 = s[r + 2][tid + 2];
        float acc = a0 * w[0] + a1 * w[1] + a2 * w[2]
                  + b0 * w[3] + b1 * w[4] + b2 * w[5]
                  + c0 * w[6] + c1 * w[7] + c2 * w[8];
        ss += acc * acc;
        outh[base + (size_t)(y0 + r) * W_ + tid] = __float2half(acc);
        a0 = b0; a1 = b1; a2 = b2;
        b0 = c0; b1 = c1; b2 = c2;
    }

    if (c < 2 * C_) {
        __shared__ float red[8];
#pragma unroll
        for (int o = 16; o > 0; o >>= 1) ss += __shfl_xor_sync(0xffffffffu, ss, o);
        if ((tid & 31) == 0) red[tid >> 5] = ss;
        __syncthreads();
        if (tid == 0) {
            float tot = 0.f;
#pragma unroll
            for (int i = 0; i < 8; ++i) tot += red[i];
            if (c < C_)
                partq[(b * C_ + c) * 16 + blockIdx.x] = tot;
            else
                partk[(b * C_ + (c - C_)) * 16 + blockIdx.x] = tot;
        }
    }
}

__global__ void norms_finish(
    const float* __restrict__ partq, const float* __restrict__ partk,
    float* __restrict__ invq, float* __restrict__ invk)
{
    int idx = blockIdx.x * blockDim.x + threadIdx.x;
    if (idx < B_ * C_ * 8) {
        float sq = partq[idx * 2] + partq[idx * 2 + 1];
        float sk = partk[idx * 2] + partk[idx * 2 + 1];
        invq[idx] = 1.f / fmaxf(sqrtf(sq), 1e-12f);
        invk[idx] = 1.f / fmaxf(sqrtf(sk), 1e-12f);
    }
}

// ---------------- split-K reduce + scale + softmax -> fp16 ---------------
__global__ void softmax_kernel(
    const float* __restrict__ gramp, const float* __restrict__ invq,
    const float* __restrict__ invk, const float* __restrict__ temp,
    __half* __restrict__ attnh)
{
    const int i = blockIdx.x % C_;
    const int bh = blockIdx.x / C_;
    const int head = bh & 7, b = bh >> 3;
    const int j = threadIdx.x;

    const long long base = (long long)bh * (C_ * C_) + i * C_ + j;
    float s = 0.f;
#pragma unroll
    for (int ks = 0; ks < KSPLIT_; ++ks)
        s += gramp[(long long)ks * (B_ * HEADS_ * C_ * C_) + base];

    s *= invq[(b * C_ + head * 24 + (i >> 3)) * 8 + (i & 7)]
       * invk[(b * C_ + head * 24 + (j >> 3)) * 8 + (j & 7)]
       * temp[head];

    __shared__ float red[8];
    float m = s;
#pragma unroll
    for (int o = 16; o > 0; o >>= 1) m = fmaxf(m, __shfl_xor_sync(0xffffffffu, m, o));
    if ((threadIdx.x & 31) == 0) red[threadIdx.x >> 5] = m;
    __syncthreads();
    m = fmaxf(fmaxf(fmaxf(red[0], red[1]), fmaxf(red[2], red[3])), fmaxf(red[4], red[5]));

    float p = expf(s - m);
    float sum = p;
#pragma unroll
    for (int o = 16; o > 0; o >>= 1) sum += __shfl_xor_sync(0xffffffffu, sum, o);
    __syncthreads();
    if ((threadIdx.x & 31) == 0) red[threadIdx.x >> 5] = sum;
    __syncthreads();
    sum = red[0] + red[1] + red[2] + red[3] + red[4] + red[5];

    attnh[base] = __float2half(p / sum);
}

// ---------------- launch -------------------------------------------------------
extern "C" void kernel_launch(void* const* d_in, const int* in_sizes, int n_in,
                              void* d_out, int out_size)
{
    const float* x      = (const float*)d_in[0];
    const float* qkv_w  = (const float*)d_in[1];
    const float* dw_w   = (const float*)d_in[2];
    const float* proj_w = (const float*)d_in[3];
    const float* temp   = (const float*)d_in[4];
    float* out = (float*)d_out;

    __half *xh, *wqh, *wph, *qkvh, *dwh, *av, *attnh;
    float *gramp, *partq, *partk, *invq, *invk;
    cudaGetSymbolAddress((void**)&xh,   g_xh);
    cudaGetSymbolAddress((void**)&wqh,  g_wqh);
    cudaGetSymbolAddress((void**)&wph,  g_wph);
    cudaGetSymbolAddress((void**)&qkvh, g_qkvh);
    cudaGetSymbolAddress((void**)&dwh,  g_dwh);
    cudaGetSymbolAddress((void**)&av,   g_av);
    cudaGetSymbolAddress((void**)&attnh, g_attnh);
    cudaGetSymbolAddress((void**)&gramp, g_gramp);
    cudaGetSymbolAddress((void**)&partq, g_partq);
    cudaGetSymbolAddress((void**)&partk, g_partk);
    cudaGetSymbolAddress((void**)&invq,  g_invq);
    cudaGetSymbolAddress((void**)&invk,  g_invk);

    cudaFuncSetAttribute(gemm_mma<QkvMap>,  cudaFuncAttributeMaxDynamicSharedMemorySize, GEMM_SMEM);
    cudaFuncSetAttribute(gemm_mma<AvMap>,   cudaFuncAttributeMaxDynamicSharedMemorySize, GEMM_SMEM);
    cudaFuncSetAttribute(gemm_mma<ProjMap>, cudaFuncAttributeMaxDynamicSharedMemorySize, GEMM_SMEM);
    cudaFuncSetAttribute(gram_mma,          cudaFuncAttributeMaxDynamicSharedMemorySize, GRAM_SMEM);

    // 0) fp16 converts
    split_h_kernel<<<(B_ * C_ * HW_ / 4 + 255) / 256, 256>>>(x, xh, B_ * C_ * HW_);
    split_h_kernel<<<(C3_ * C_ / 4 + 255) / 256, 256>>>(qkv_w, wqh, C3_ * C_);
    split_h_kernel<<<(C_ * C_ / 4 + 255) / 256, 256>>>(proj_w, wph, C_ * C_);

    // 1) qkv = qkv_w @ x
    {
        QkvMap m{wqh, xh, qkvh};
        gemm_mma<QkvMap><<<dim3(HW_ / 128, C3_ / 96, B_), 384, GEMM_SMEM>>>(m, C_);
    }
    // 2) depthwise 3x3 (band tiles) + norm partials
    dw_kernel<<<dim3(16, B_ * C3_), 256>>>(qkvh, dw_w, dwh, partq, partk);
    // 3) norms
    norms_finish<<<(B_ * C_ * 8 + 255) / 256, 256>>>(partq, partk, invq, invk);
    // 4) gram partials (split-K = 4)
    gram_mma<<<dim3(2, 2, B_ * HEADS_ * KSPLIT_), 256, GRAM_SMEM>>>(dwh, gramp);
    // 5) softmax
    softmax_kernel<<<B_ * HEADS_ * C_, C_>>>(gramp, invq, invk, temp, attnh);
    // 6) av = attn @ v
    {
        AvMap m{attnh, dwh, av};
        gemm_mma<AvMap><<<dim3(HW_ / HEADS_ / 128, C_ / 96, B_ * HEADS_), 384, GEMM_SMEM>>>(m, C_);
    }
    // 7) out = proj_w @ av
    {
        ProjMap m{wph, av, out};
        gemm_mma<ProjMap><<<dim3(HW_ / 128, C_ / 96, B_), 384, GEMM_SMEM>>>(m, C_);
    }
}